// round 10
// baseline (speedup 1.0000x reference)
#include <cuda_runtime.h>

#define NB 8
#define NP 4096
#define NS 1024

// ---------------- device scratch (static: no allocation allowed) ----------------
__device__ float gPQ0[NB*NP*32];
__device__ float gPQ1[NB*NP*64];
__device__ float gPQ2[NB*NP*64];
__device__ int   gIdx0[NB*NS*16];
__device__ int   gIdx1[NB*NS*32];
__device__ int   gIdx2[NB*NS*128];

// packed fp32x2 FMA (sm_100+): 2 MACs/instr
__device__ __forceinline__ float2 ffma2(float2 a, float2 b, float2 c){
    unsigned long long au, bu, cu, du;
    au = *reinterpret_cast<const unsigned long long*>(&a);
    bu = *reinterpret_cast<const unsigned long long*>(&b);
    cu = *reinterpret_cast<const unsigned long long*>(&c);
    asm("fma.rn.f32x2 %0, %1, %2, %3;" : "=l"(du) : "l"(au), "l"(bu), "l"(cu));
    return *reinterpret_cast<float2*>(&du);
}
__device__ __forceinline__ float2 f2lo(float4 v){ return make_float2(v.x, v.y); }
__device__ __forceinline__ float2 f2hi(float4 v){ return make_float2(v.z, v.w); }

// ---------------- FPS (unchanged, passing) ----------------
__global__ void __launch_bounds__(1024) fps_kernel(
    const float* __restrict__ xyz, float* __restrict__ newxyz)
{
    extern __shared__ float sfm[];
    __shared__ unsigned long long swarp[32];
    __shared__ float scent[3];
    float* sx = sfm; float* sy = sfm + NP; float* sz = sfm + 2*NP;

    const int b = blockIdx.x, tid = threadIdx.x;
    const float* xb = xyz + (size_t)b * NP * 3;

    float px[4], py[4], pz[4], dist[4];
#pragma unroll
    for (int i = 0; i < 4; i++){
        int p = tid + 1024*i;
        px[i] = xb[3*p]; py[i] = xb[3*p+1]; pz[i] = xb[3*p+2];
        sx[p] = px[i]; sy[p] = py[i]; sz[p] = pz[i];
        dist[i] = 1e10f;
    }
    if (tid == 0){ scent[0] = px[0]; scent[1] = py[0]; scent[2] = pz[0]; }
    __syncthreads();

    for (int it = 0; it < NS; ++it){
        const float cx = scent[0], cy = scent[1], cz = scent[2];
        if (tid == 0){
            float* o = newxyz + ((size_t)b * NS + it) * 3;
            o[0] = cx; o[1] = cy; o[2] = cz;
        }
        float m; unsigned mi;
#pragma unroll
        for (int i = 0; i < 4; i++){
            float dx = px[i]-cx, dy = py[i]-cy, dz = pz[i]-cz;
            float d = __fadd_rn(__fadd_rn(__fmul_rn(dx,dx), __fmul_rn(dy,dy)), __fmul_rn(dz,dz));
            float nd = fminf(dist[i], d);
            dist[i] = nd;
            if (i == 0){ m = nd; mi = (unsigned)tid; }
            else if (nd > m){ m = nd; mi = (unsigned)(tid + 1024*i); }
        }
        unsigned long long best = ((unsigned long long)__float_as_uint(m) << 32)
                                | (unsigned long long)(0xFFFFFFFFu - mi);
#pragma unroll
        for (int off = 16; off; off >>= 1){
            unsigned long long o = __shfl_down_sync(0xFFFFFFFFu, best, off);
            if (o > best) best = o;
        }
        if ((tid & 31) == 0) swarp[tid >> 5] = best;
        __syncthreads();
        if (tid < 32){
            unsigned long long v = swarp[tid];
#pragma unroll
            for (int off = 16; off; off >>= 1){
                unsigned long long o = __shfl_down_sync(0xFFFFFFFFu, v, off);
                if (o > v) v = o;
            }
            if (tid == 0){
                unsigned w = 0xFFFFFFFFu - (unsigned)(v & 0xFFFFFFFFull);
                scent[0] = sx[w]; scent[1] = sy[w]; scent[2] = sz[w];
            }
        }
        __syncthreads();
    }
}

// ---------------- PQ precompute (unchanged, passing) ----------------
__global__ void __launch_bounds__(160) pq_kernel(
    const float* __restrict__ xyz, const float* __restrict__ feat,
    const float* __restrict__ w00, const float* __restrict__ b00,
    const float* __restrict__ w10, const float* __restrict__ b10,
    const float* __restrict__ w20, const float* __restrict__ b20)
{
    __shared__ float sin_[8*68];
    const int tid = threadIdx.x;
    const float* wrow; float bias; float* dst; int C, ch;
    if (tid < 32)      { wrow = w00 + tid*67;      bias = b00[tid];    dst = gPQ0; C = 32; ch = tid; }
    else if (tid < 96) { wrow = w10 + (tid-32)*67; bias = b10[tid-32]; dst = gPQ1; C = 64; ch = tid-32; }
    else               { wrow = w20 + (tid-96)*67; bias = b20[tid-96]; dst = gPQ2; C = 64; ch = tid-96; }
    float wreg[67];
#pragma unroll
    for (int i = 0; i < 67; i++) wreg[i] = wrow[i];

    for (int grp = 0; grp < 4; grp++){
        int gbase = blockIdx.x * 32 + grp * 8;
        __syncthreads();
        for (int t = tid; t < 8*67; t += 160){
            int pt = t / 67, c = t - 67*pt;
            int g = gbase + pt;
            sin_[pt*68 + c] = (c < 3) ? xyz[(size_t)g*3 + c] : feat[(size_t)g*64 + (c-3)];
        }
        __syncthreads();
#pragma unroll 1
        for (int pt = 0; pt < 8; pt++){
            const float* inp = &sin_[pt*68];
            float a0 = bias, a1 = 0.f;
#pragma unroll
            for (int i = 0; i < 8; i++){
                float4 v0 = *reinterpret_cast<const float4*>(inp + 8*i);
                float4 v1 = *reinterpret_cast<const float4*>(inp + 8*i + 4);
                a0 = fmaf(v0.x, wreg[8*i+0], a0); a0 = fmaf(v0.y, wreg[8*i+1], a0);
                a0 = fmaf(v0.z, wreg[8*i+2], a0); a0 = fmaf(v0.w, wreg[8*i+3], a0);
                a1 = fmaf(v1.x, wreg[8*i+4], a1); a1 = fmaf(v1.y, wreg[8*i+5], a1);
                a1 = fmaf(v1.z, wreg[8*i+6], a1); a1 = fmaf(v1.w, wreg[8*i+7], a1);
            }
            a0 = fmaf(inp[64], wreg[64], a0);
            a1 = fmaf(inp[65], wreg[65], a1);
            a0 = fmaf(inp[66], wreg[66], a0);
            dst[(size_t)(gbase + pt) * C + ch] = a0 + a1;
        }
    }
}

// ---------------- ball query (unchanged, passing) ----------------
__global__ void __launch_bounds__(128) ball_kernel(
    const float* __restrict__ xyz, const float* __restrict__ newxyz)
{
    const int bs = blockIdx.x;
    const int b = bs >> 10;
    const int tid = threadIdx.x;
    const int w = tid >> 5, lane = tid & 31;
    const float cx = newxyz[(size_t)bs*3+0];
    const float cy = newxyz[(size_t)bs*3+1];
    const float cz = newxyz[(size_t)bs*3+2];
    const float nn = __fadd_rn(__fadd_rn(__fmul_rn(cx,cx), __fmul_rn(cy,cy)), __fmul_rn(cz,cz));
    __shared__ int cnt[3], wcnt[3][4], sfirst[3];
    if (tid < 3){ cnt[tid] = 0; sfirst[tid] = 0; }
    __syncthreads();
    const float* xb = xyz + (size_t)b * NP * 3;

    for (int jb = 0; jb < NP; jb += 128){
        int j = jb + tid;
        float x = xb[3*j], y = xb[3*j+1], z = xb[3*j+2];
        float pp  = __fadd_rn(__fadd_rn(__fmul_rn(x,x), __fmul_rn(y,y)), __fmul_rn(z,z));
        float dot = __fadd_rn(__fadd_rn(__fmul_rn(cx,x), __fmul_rn(cy,y)), __fmul_rn(cz,z));
        float sqd = __fsub_rn(__fadd_rn(nn, pp), __fmul_rn(2.0f, dot));
        bool in0 = !(sqd > 0.01f);
        bool in1 = !(sqd > 0.04f);
        bool in2 = !(sqd > 0.16f);
        unsigned m0 = __ballot_sync(0xFFFFFFFFu, in0);
        unsigned m1 = __ballot_sync(0xFFFFFFFFu, in1);
        unsigned m2 = __ballot_sync(0xFFFFFFFFu, in2);
        if (lane == 0){ wcnt[0][w]=__popc(m0); wcnt[1][w]=__popc(m1); wcnt[2][w]=__popc(m2); }
        __syncthreads();
        unsigned lm = (1u << lane) - 1u;
        int b0 = cnt[0], b1 = cnt[1], b2 = cnt[2];
        for (int ww = 0; ww < w; ww++){ b0 += wcnt[0][ww]; b1 += wcnt[1][ww]; b2 += wcnt[2][ww]; }
        if (in0){ int p = b0 + __popc(m0 & lm); if (p == 0) sfirst[0] = j; if (p < 16)  gIdx0[(size_t)bs*16  + p] = j; }
        if (in1){ int p = b1 + __popc(m1 & lm); if (p == 0) sfirst[1] = j; if (p < 32)  gIdx1[(size_t)bs*32  + p] = j; }
        if (in2){ int p = b2 + __popc(m2 & lm); if (p == 0) sfirst[2] = j; if (p < 128) gIdx2[(size_t)bs*128 + p] = j; }
        __syncthreads();
        if (tid == 0){
            cnt[0] += wcnt[0][0]+wcnt[0][1]+wcnt[0][2]+wcnt[0][3];
            cnt[1] += wcnt[1][0]+wcnt[1][1]+wcnt[1][2]+wcnt[1][3];
            cnt[2] += wcnt[2][0]+wcnt[2][1]+wcnt[2][2]+wcnt[2][3];
        }
        __syncthreads();
        if (cnt[0] >= 16 && cnt[1] >= 32 && cnt[2] >= 128) break;
    }
    int f0 = sfirst[0], f1 = sfirst[1], f2 = sfirst[2];
    for (int q = cnt[0] + tid; q < 16;  q += 128) gIdx0[(size_t)bs*16  + q] = f0;
    for (int q = cnt[1] + tid; q < 32;  q += 128) gIdx1[(size_t)bs*32  + q] = f1;
    for (int q = cnt[2] + tid; q < 128; q += 128) gIdx2[(size_t)bs*128 + q] = f2;
}

// ---------------- unified MLP2+MLP3+maxpool: 512 thr, 2-D warp/lane mapping ----------------
// lane -> (lr=lane/8, lc=lane%8); warp -> (rb=w%NWR, cb=w/NWR).
// rows  r = rb*4TR + lr + 4i  (4 distinct rows per warp a-load, broadcast x8)
// cols  c = cb*8TC + lc + 8j  (8 distinct w-rows per warp load = one 128B wavefront,
//                              bank starts lc*(P%32==4) all distinct: conflict-free)
template<int SCALE,int BC,int K,int C1,int C2,int C3,int P1,int P2,int NWR2,int NWR3>
__global__ void __launch_bounds__(512,1) mlp_kernel(
    const float* __restrict__ w1,
    const float* __restrict__ w2, const float* __restrict__ b2,
    const float* __restrict__ w3, const float* __restrict__ b3,
    const float* __restrict__ newxyz, float* __restrict__ out, int off)
{
    constexpr int NT = 512;
    constexpr int R  = BC*K;
    const float* PQ  = (SCALE==0) ? gPQ0  : (SCALE==1) ? gPQ1  : gPQ2;
    const int*   IDX = (SCALE==0) ? gIdx0 : (SCALE==1) ? gIdx1 : gIdx2;

    extern __shared__ float sm[];
    float* h1  = sm;                    // R  * P1
    float* h2  = h1  + R*P1;            // R  * P2
    float* w2s = h2  + R*P2;            // C2 * P1
    float* w3s = w2s + C2*P1;           // C3 * P2
    float* Rs  = w3s + C3*P2;           // BC * C1
    int*   nix = (int*)(Rs + BC*C1);    // R
    int*   mbuf= nix + R;               // BC * C3

    const int tid  = threadIdx.x;
    const int wid  = tid >> 5;
    const int lr   = (tid & 31) >> 3;   // 0..3
    const int lc   = tid & 7;           // 0..7
    const int bs0  = blockIdx.x * BC;
    const int b    = bs0 >> 10;

    for (int e = tid; e < C2*(C1/4); e += NT){
        int c = e/(C1/4), q = e - c*(C1/4);
        *reinterpret_cast<float4*>(&w2s[c*P1 + 4*q]) = reinterpret_cast<const float4*>(w2)[e];
    }
    for (int e = tid; e < C3*(C2/4); e += NT){
        int c = e/(C2/4), q = e - c*(C2/4);
        *reinterpret_cast<float4*>(&w3s[c*P2 + 4*q]) = reinterpret_cast<const float4*>(w3)[e];
    }
    for (int e = tid; e < R; e += NT) nix[e] = IDX[(size_t)bs0*K + e];
    for (int e = tid; e < BC*C3; e += NT) mbuf[e] = 0;   // int 0 == float 0.0f (relu floor)
    for (int e = tid; e < BC*C1; e += NT){
        int c = e / C1, ch = e - c*C1;
        const float* wr = w1 + ch*67;
        const float* ce = newxyz + (size_t)(bs0 + c)*3;
        Rs[e] = fmaf(wr[2], ce[2], fmaf(wr[1], ce[1], wr[0]*ce[0]));
    }
    __syncthreads();

    // gather + h1 = relu(PQ[nix] - Rs)
    {
        constexpr int C1v = C1/4;
        const float4* PQ4 = reinterpret_cast<const float4*>(PQ + (size_t)b * NP * C1);
        for (int e = tid; e < R*C1v; e += NT){
            int r = e / C1v, q = e - r*C1v;
            float4 v  = PQ4[(size_t)nix[r]*C1v + q];
            float4 rv = *reinterpret_cast<const float4*>(&Rs[(r/K)*C1 + 4*q]);
            v.x = fmaxf(v.x - rv.x, 0.f); v.y = fmaxf(v.y - rv.y, 0.f);
            v.z = fmaxf(v.z - rv.z, 0.f); v.w = fmaxf(v.w - rv.w, 0.f);
            *reinterpret_cast<float4*>(&h1[r*P1 + 4*q]) = v;
        }
    }
    __syncthreads();

    // ---- layer 2: H2[R x C2] = relu(H1 @ W2^T + b2) ----
    {
        constexpr int TR = R/(NWR2*4), TC = C2*NWR2/128;   // TC = C2/(NWC*8), NWC=16/NWR2
        const int rb = wid % NWR2, cb = wid / NWR2;
        const int r0 = rb*4*TR + lr;
        const int c0 = cb*8*TC + lc;
        float2 acc[TR][TC];
#pragma unroll
        for (int i = 0; i < TR; i++)
#pragma unroll
            for (int j = 0; j < TC; j++) acc[i][j] = make_float2(0.f, 0.f);
#pragma unroll 2
        for (int kk = 0; kk < C1; kk += 4){
            float4 a[TR];
#pragma unroll
            for (int i = 0; i < TR; i++)
                a[i] = *reinterpret_cast<const float4*>(&h1[(r0 + 4*i)*P1 + kk]);
#pragma unroll
            for (int j = 0; j < TC; j++){
                float4 w = *reinterpret_cast<const float4*>(&w2s[(c0 + 8*j)*P1 + kk]);
#pragma unroll
                for (int i = 0; i < TR; i++){
                    acc[i][j] = ffma2(f2lo(a[i]), f2lo(w), acc[i][j]);
                    acc[i][j] = ffma2(f2hi(a[i]), f2hi(w), acc[i][j]);
                }
            }
        }
#pragma unroll
        for (int j = 0; j < TC; j++){
            float bb = b2[c0 + 8*j];
#pragma unroll
            for (int i = 0; i < TR; i++)
                h2[(r0 + 4*i)*P2 + c0 + 8*j] = fmaxf(acc[i][j].x + acc[i][j].y + bb, 0.f);
        }
    }
    __syncthreads();

    // ---- layer 3 + fused maxpool (all TR rows of a thread share one center: 4*TR <= K) ----
    {
        constexpr int TR = R/(NWR3*4), TC = C3*NWR3/128;
        static_assert(4*TR <= K, "rows per thread must stay within one center");
        const int rb = wid % NWR3, cb = wid / NWR3;
        const int r0 = rb*4*TR + lr;
        const int c0 = cb*8*TC + lc;
        const int cen = (rb*4*TR) / K;
        float2 acc[TR][TC];
#pragma unroll
        for (int i = 0; i < TR; i++)
#pragma unroll
            for (int j = 0; j < TC; j++) acc[i][j] = make_float2(0.f, 0.f);
#pragma unroll 2
        for (int kk = 0; kk < C2; kk += 4){
            float4 a[TR];
#pragma unroll
            for (int i = 0; i < TR; i++)
                a[i] = *reinterpret_cast<const float4*>(&h2[(r0 + 4*i)*P2 + kk]);
#pragma unroll
            for (int j = 0; j < TC; j++){
                float4 w = *reinterpret_cast<const float4*>(&w3s[(c0 + 8*j)*P2 + kk]);
#pragma unroll
                for (int i = 0; i < TR; i++){
                    acc[i][j] = ffma2(f2lo(a[i]), f2lo(w), acc[i][j]);
                    acc[i][j] = ffma2(f2hi(a[i]), f2hi(w), acc[i][j]);
                }
            }
        }
#pragma unroll
        for (int j = 0; j < TC; j++){
            float bb = b3[c0 + 8*j];
            float vm = -1e30f;
#pragma unroll
            for (int i = 0; i < TR; i++)
                vm = fmaxf(vm, acc[i][j].x + acc[i][j].y + bb);
            atomicMax(&mbuf[cen*C3 + c0 + 8*j], __float_as_int(vm));
        }
    }
    __syncthreads();

    for (int e = tid; e < BC*C3; e += NT){
        int c = e / C3, col = e - c*C3;
        out[(size_t)(bs0 + c)*320 + off + col] = __int_as_float(mbuf[e]);
    }
}

// smem sizes (bytes)
template<int BC,int K,int C1,int C2,int C3,int P1,int P2>
constexpr int mlp_smem(){
    return (BC*K*P1 + BC*K*P2 + C2*P1 + C3*P2 + BC*C1)*4 + (BC*K + BC*C3)*4;
}

// ---------------- launch ----------------
extern "C" void kernel_launch(void* const* d_in, const int* in_sizes, int n_in,
                              void* d_out, int out_size)
{
    const float* xyz  = (const float*)d_in[0];
    const float* feat = (const float*)d_in[1];
    const float* W[3][3]; const float* Bi[3][3];
    for (int i = 0; i < 3; i++)
        for (int j = 0; j < 3; j++){
            W[i][j]  = (const float*)d_in[2 + i*6 + j*2];
            Bi[i][j] = (const float*)d_in[3 + i*6 + j*2];
        }
    float* newxyz   = (float*)d_out;                 // (B, S, 3)
    float* feat_out = (float*)d_out + NB*NS*3;       // (B, S, 320)

    // scale0: BC=16 (R=256): L2 NWR=16 (TR4,TC4); L3 NWR=16 (TR4,TC8)
    constexpr int SM0 = mlp_smem<16,16,32,32,64,36,36>();
    // scale1: BC=4 (R=128): L2 NWR=8 (TR4,TC4); L3 NWR=8 (TR4,TC8)
    constexpr int SM1 = mlp_smem<4,32,64,64,128,68,68>();
    // scale2: BC=1 (R=128): L2 NWR=8 (TR4,TC6); L3 NWR=8 (TR4,TC8)
    constexpr int SM2 = mlp_smem<1,128,64,96,128,68,100>();
    constexpr int SMF = 3*NP*4;

    cudaFuncSetAttribute((const void*)fps_kernel,
                         cudaFuncAttributeMaxDynamicSharedMemorySize, SMF);
    cudaFuncSetAttribute((const void*)mlp_kernel<0,16,16,32,32,64,36,36,16,16>,
                         cudaFuncAttributeMaxDynamicSharedMemorySize, SM0);
    cudaFuncSetAttribute((const void*)mlp_kernel<1,4,32,64,64,128,68,68,8,8>,
                         cudaFuncAttributeMaxDynamicSharedMemorySize, SM1);
    cudaFuncSetAttribute((const void*)mlp_kernel<2,1,128,64,96,128,68,100,8,8>,
                         cudaFuncAttributeMaxDynamicSharedMemorySize, SM2);

    fps_kernel<<<NB, 1024, SMF>>>(xyz, newxyz);
    pq_kernel<<<NB*NP/32, 160>>>(xyz, feat,
        W[0][0], Bi[0][0], W[1][0], Bi[1][0], W[2][0], Bi[2][0]);
    ball_kernel<<<NB*NS, 128>>>(xyz, newxyz);

    mlp_kernel<0,16,16,32,32,64,36,36,16,16><<<NB*NS/16, 512, SM0>>>(
        W[0][0], W[0][1], Bi[0][1], W[0][2], Bi[0][2], newxyz, feat_out, 0);
    mlp_kernel<1,4,32,64,64,128,68,68,8,8><<<NB*NS/4, 512, SM1>>>(
        W[1][0], W[1][1], Bi[1][1], W[1][2], Bi[1][2], newxyz, feat_out, 64);
    mlp_kernel<2,1,128,64,96,128,68,100,8,8><<<NB*NS, 512, SM2>>>(
        W[2][0], W[2][1], Bi[2][1], W[2][2], Bi[2][2], newxyz, feat_out, 192);
}